// round 12
// baseline (speedup 1.0000x reference)
#include <cuda_runtime.h>
#include <cuda_fp16.h>
#include <math.h>
#include <stdint.h>

#define T_TOK 8192
#define D_DIM 1024
#define F_DIM 4096
#define E_NUM 8
#define A_TOT (T_TOK * 2)

// ---------------- scratch (device globals; no allocations allowed) ----------
__device__ int   g_cnt[E_NUM];
__device__ int   g_off[E_NUM];
__device__ int   g_cur[E_NUM];
__device__ int   g_top[T_TOK][2];
__device__ float g_gate[T_TOK][2];
__device__ int   g_rowtok[A_TOT];
__device__ float g_rowgate[A_TOT];

// fp16 tensors (raw ushort bits), single plane everywhere
__device__ unsigned short g_x16[(size_t)T_TOK * D_DIM];
__device__ unsigned short g_w1t[(size_t)E_NUM * F_DIM * D_DIM];  // [e][f][d]
__device__ unsigned short g_w2t[(size_t)E_NUM * D_DIM * F_DIM];  // [e][d][f]
__device__ unsigned short g_h16[(size_t)A_TOT * F_DIM];          // [row][f]

// ---------------- helpers -----------------------------------------------------
__device__ __forceinline__ uint32_t smem_u32(const void* p) {
    uint32_t a;
    asm("{ .reg .u64 t; cvta.to.shared.u64 t, %1; cvt.u32.u64 %0, t; }"
        : "=r"(a) : "l"(p));
    return a;
}
#define SWZ(o) ((o) ^ (((o) >> 3) & 0x70))

__device__ __forceinline__ void cpa16(uint32_t d, const void* s, uint32_t n) {
    asm volatile("cp.async.cg.shared.global [%0], [%1], 16, %2;"
                 :: "r"(d), "l"(s), "r"(n) : "memory");
}
#define CP_COMMIT() asm volatile("cp.async.commit_group;" ::: "memory")
#define CP_WAIT1()  asm volatile("cp.async.wait_group 1;" ::: "memory")

#define LDSM4(r, a)                                                      \
    asm volatile("ldmatrix.sync.aligned.m8n8.x4.shared.b16 "             \
                 "{%0,%1,%2,%3}, [%4];"                                  \
                 : "=r"((r)[0]), "=r"((r)[1]), "=r"((r)[2]), "=r"((r)[3])\
                 : "r"(a))

__device__ __forceinline__ void mma16816(float* c, const uint32_t* a,
                                         const uint32_t* b) {
    asm volatile(
        "mma.sync.aligned.m16n8k16.row.col.f32.f16.f16.f32 "
        "{%0,%1,%2,%3}, {%4,%5,%6,%7}, {%8,%9}, {%0,%1,%2,%3};"
        : "+f"(c[0]), "+f"(c[1]), "+f"(c[2]), "+f"(c[3])
        : "r"(a[0]), "r"(a[1]), "r"(a[2]), "r"(a[3]), "r"(b[0]), "r"(b[1]));
}

__device__ __forceinline__ unsigned short to_h16(float v) {
    __half hb = __float2half_rn(v);
    return *reinterpret_cast<unsigned short*>(&hb);
}
__device__ __forceinline__ float gelu_tanh(float v) {
    float c = 0.7978845608028654f * (v + 0.044715f * v * v * v);
    return 0.5f * v * (1.0f + tanhf(c));
}

// ---------------- init + x conversion (fused) ---------------------------------
__global__ void conv_x_kernel(const float* __restrict__ x,
                              float* __restrict__ out) {
    size_t v = (size_t)blockIdx.x * blockDim.x + threadIdx.x;  // float4 idx
    ((float4*)out)[v] = make_float4(0.f, 0.f, 0.f, 0.f);
    float4 f = ((const float4*)x)[v];
    ushort4 h;
    h.x = to_h16(f.x);
    h.y = to_h16(f.y);
    h.z = to_h16(f.z);
    h.w = to_h16(f.w);
    ((ushort4*)g_x16)[v] = h;
    if (blockIdx.x == 0 && threadIdx.x < E_NUM) {
        g_cnt[threadIdx.x] = 0;
        g_cur[threadIdx.x] = 0;
    }
}

// ---------------- router: warp/token, float4 x and rw loads -------------------
__global__ void router_kernel(const float* __restrict__ x,
                              const float* __restrict__ rw) {
    int gwarp = (blockIdx.x * blockDim.x + threadIdx.x) >> 5;
    int lane  = threadIdx.x & 31;
    if (gwarp >= T_TOK) return;
    const float4* xr4 = (const float4*)(x + (size_t)gwarp * D_DIM);

    float logits[E_NUM];
#pragma unroll
    for (int e = 0; e < E_NUM; e++) logits[e] = 0.0f;

#pragma unroll
    for (int i = 0; i < 8; i++) {
        int q = lane + 32 * i;          // float4 index; k = 4q..4q+3
        float4 xv = xr4[q];
        const float4* rr = (const float4*)(rw + (size_t)(4 * q) * E_NUM);
#pragma unroll
        for (int j = 0; j < 4; j++) {
            float xs = (j == 0) ? xv.x : (j == 1) ? xv.y : (j == 2) ? xv.z : xv.w;
            float4 r0 = rr[2 * j];
            float4 r1 = rr[2 * j + 1];
            logits[0] += xs * r0.x;
            logits[1] += xs * r0.y;
            logits[2] += xs * r0.z;
            logits[3] += xs * r0.w;
            logits[4] += xs * r1.x;
            logits[5] += xs * r1.y;
            logits[6] += xs * r1.z;
            logits[7] += xs * r1.w;
        }
    }
#pragma unroll
    for (int e = 0; e < E_NUM; e++) {
#pragma unroll
        for (int o = 16; o > 0; o >>= 1)
            logits[e] += __shfl_xor_sync(0xffffffffu, logits[e], o);
    }

    if (lane == 0) {
        int i0 = 0;
#pragma unroll
        for (int e = 1; e < E_NUM; e++)
            if (logits[e] > logits[i0]) i0 = e;
        int i1 = (i0 == 0) ? 1 : 0;
#pragma unroll
        for (int e = 0; e < E_NUM; e++) {
            if (e == i0) continue;
            if (logits[e] > logits[i1]) i1 = e;
        }
        float g0 = 1.0f / (1.0f + expf(logits[i1] - logits[i0]));
        float g1 = 1.0f - g0;
        g_top[gwarp][0]  = i0;
        g_top[gwarp][1]  = i1;
        g_gate[gwarp][0] = g0;
        g_gate[gwarp][1] = g1;
        atomicAdd(&g_cnt[i0], 1);
        atomicAdd(&g_cnt[i1], 1);
    }
}

__global__ void offsets_kernel() {
    if (threadIdx.x == 0 && blockIdx.x == 0) {
        int run = 0;
#pragma unroll
        for (int e = 0; e < E_NUM; e++) {
            g_off[e] = run;
            run += g_cnt[e];
            g_cur[e] = 0;
        }
    }
}

__global__ void place_kernel() {
    int t = blockIdx.x * blockDim.x + threadIdx.x;
    if (t >= T_TOK) return;
#pragma unroll
    for (int s = 0; s < 2; s++) {
        int e = g_top[t][s];
        int p = g_off[e] + atomicAdd(&g_cur[e], 1);
        g_rowtok[p]  = t;
        g_rowgate[p] = g_gate[t][s];
    }
}

// ---------------- weight transposes (fp32 -> fp16, K-major) -------------------
__global__ void tw1_kernel(const float* __restrict__ w1) {
    __shared__ float t[32][33];
    int e = blockIdx.z, f0 = blockIdx.x * 32, d0 = blockIdx.y * 32;
    int tx = threadIdx.x, ty = threadIdx.y;
#pragma unroll
    for (int r = 0; r < 4; r++)
        t[ty + 8 * r][tx] =
            w1[((size_t)e * D_DIM + d0 + ty + 8 * r) * F_DIM + f0 + tx];
    __syncthreads();
#pragma unroll
    for (int r = 0; r < 4; r++) {
        float v = t[tx][ty + 8 * r];  // = w1[e][d0+tx][f0+ty+8r]
        size_t idx = ((size_t)e * F_DIM + f0 + ty + 8 * r) * D_DIM + d0 + tx;
        g_w1t[idx] = to_h16(v);
    }
}

__global__ void tw2_kernel(const float* __restrict__ w2) {
    __shared__ float t[32][33];
    int e = blockIdx.z, f0 = blockIdx.x * 32, d0 = blockIdx.y * 32;
    int tx = threadIdx.x, ty = threadIdx.y;
#pragma unroll
    for (int r = 0; r < 4; r++)
        t[ty + 8 * r][tx] =
            w2[((size_t)e * F_DIM + f0 + ty + 8 * r) * D_DIM + d0 + tx];
    __syncthreads();
#pragma unroll
    for (int r = 0; r < 4; r++) {
        float v = t[tx][ty + 8 * r];  // = w2[e][f0+tx][d0+ty+8r]
        size_t idx = ((size_t)e * D_DIM + d0 + ty + 8 * r) * F_DIM + f0 + tx;
        g_w2t[idx] = to_h16(v);
    }
}

// ---------------- fp16 mma GEMM core ------------------------------------------
// CTA tile 128x128, K-chunk 64 (128B rows, SW128), 8 warps (2M x 4N),
// warp tile 64x32, 3-stage cp.async pipeline, 1 MMA per (mi,ni,k16).
// 2 CTAs/SM. B loaded with x4 ldmatrix.
#define STAGE_BYTES 32768
#define SOFF_A 0
#define SOFF_B 16384
#define NSTAGE 3
#define SMEM_GEMM (NSTAGE * STAGE_BYTES)

#define GEMM_COMPUTE_CHUNK(st)                                               \
    _Pragma("unroll")                                                        \
    for (int ks = 0; ks < 4; ks++) {                                         \
        uint32_t av[4][4], bbf[2][4];                                        \
        uint32_t arow = warpM + (lane & 15);                                 \
        uint32_t acol = ks * 32 + ((lane >> 4) << 4);                        \
        _Pragma("unroll")                                                    \
        for (int mi = 0; mi < 4; mi++) {                                     \
            uint32_t ad = (st) + SOFF_A + SWZ((arow + 16 * mi) * 128 + acol);\
            LDSM4(av[mi], ad);                                               \
        }                                                                    \
        uint32_t bni = (lane >> 4) << 3;                                     \
        uint32_t bkh = ((lane >> 3) & 1) << 4;                               \
        _Pragma("unroll")                                                    \
        for (int nip = 0; nip < 2; nip++) {                                  \
            uint32_t bd = (st) + SOFF_B +                                    \
                SWZ((warpN + 16 * nip + bni + (lane & 7)) * 128 +            \
                    ks * 32 + bkh);                                          \
            LDSM4(bbf[nip], bd);                                             \
        }                                                                    \
        _Pragma("unroll")                                                    \
        for (int ni = 0; ni < 4; ni++)                                       \
            _Pragma("unroll")                                                \
            for (int mi = 0; mi < 4; mi++)                                   \
                mma16816(acc[mi][ni], av[mi], &bbf[ni >> 1][2 * (ni & 1)]);  \
    }

#define GEMM_LOAD_CHUNK(stage, pa, pb, k0)                                   \
    {                                                                        \
        uint32_t st_ = sb + (stage) * STAGE_BYTES;                           \
        _Pragma("unroll")                                                    \
        for (int i = 0; i < 4; i++) {                                        \
            cpa16(st_ + SOFF_A + dsw[i], (pa) + aoff[i] + (k0), an[i]);      \
            cpa16(st_ + SOFF_B + dsw[i], (pb) + boff[i] + (k0), 16u);        \
        }                                                                    \
    }

// ---------------- GEMM1: H = gelu(gather(X) @ w1t[e]^T) -----------------------
__global__ __launch_bounds__(256, 2) void gemm1_mma() {
    const int e   = blockIdx.z;
    const int cnt = g_cnt[e];
    const int m0  = blockIdx.x * 128;
    if (m0 >= cnt) return;
    const int base = g_off[e];
    const int n0   = blockIdx.y * 128;

    extern __shared__ char smem[];
    const uint32_t sb = smem_u32(smem);
    const int tid = threadIdx.x, lane = tid & 31, wid = tid >> 5;
    const uint32_t warpM = (wid & 1) * 64, warpN = (wid >> 1) * 32;

    const int colg = tid & 7;
    const int rq   = tid >> 3;
    size_t aoff[4], boff[4];
    uint32_t an[4], dsw[4];
#pragma unroll
    for (int i = 0; i < 4; i++) {
        int r = rq + 32 * i;
        dsw[i] = SWZ((uint32_t)(r * 128 + colg * 16));
        bool v = (m0 + r) < cnt;
        aoff[i] = v ? (size_t)g_rowtok[base + m0 + r] * D_DIM : 0;
        an[i]   = v ? 16u : 0u;
        boff[i] = ((size_t)e * F_DIM + n0 + r) * D_DIM;
    }

    float acc[4][4][4];
#pragma unroll
    for (int a = 0; a < 4; a++)
#pragma unroll
        for (int b = 0; b < 4; b++)
#pragma unroll
            for (int c = 0; c < 4; c++) acc[a][b][c] = 0.0f;

    const int NC = D_DIM / 64;  // 16
    const int kbase = colg * 8;
    GEMM_LOAD_CHUNK(0, g_x16, g_w1t, kbase);
    CP_COMMIT();
    GEMM_LOAD_CHUNK(1, g_x16, g_w1t, 64 + kbase);
    CP_COMMIT();

    for (int c = 0; c < NC; c++) {
        CP_WAIT1();
        __syncthreads();
        int cn = c + 2;
        if (cn < NC)
            GEMM_LOAD_CHUNK(cn % 3, g_x16, g_w1t, cn * 64 + kbase);
        CP_COMMIT();
        uint32_t st = sb + (c % 3) * STAGE_BYTES;
        GEMM_COMPUTE_CHUNK(st)
    }

    // epilogue: gelu -> fp16 -> store to g_h16
#pragma unroll
    for (int mi = 0; mi < 4; mi++)
#pragma unroll
        for (int p = 0; p < 2; p++) {
            int gm = m0 + (int)warpM + mi * 16 + (lane >> 2) + 8 * p;
            if (gm < cnt) {
                size_t rb = (size_t)(base + gm) * F_DIM;
#pragma unroll
                for (int ni = 0; ni < 4; ni++) {
                    int n = n0 + (int)warpN + ni * 8 + 2 * (lane & 3);
                    float v0 = gelu_tanh(acc[mi][ni][2 * p]);
                    float v1 = gelu_tanh(acc[mi][ni][2 * p + 1]);
                    *(ushort2*)(g_h16 + rb + n) =
                        make_ushort2(to_h16(v0), to_h16(v1));
                }
            }
        }
}

// ---------------- GEMM2: out[tok] += gate * (H @ w2t[e]^T) --------------------
__global__ __launch_bounds__(256, 2) void gemm2_mma(float* __restrict__ out) {
    const int e   = blockIdx.z;
    const int cnt = g_cnt[e];
    const int m0  = blockIdx.x * 128;
    if (m0 >= cnt) return;
    const int base = g_off[e];
    const int d0   = blockIdx.y * 128;

    extern __shared__ char smem[];
    const uint32_t sb = smem_u32(smem);
    const int tid = threadIdx.x, lane = tid & 31, wid = tid >> 5;
    const uint32_t warpM = (wid & 1) * 64, warpN = (wid >> 1) * 32;

    const int colg = tid & 7;
    const int rq   = tid >> 3;
    size_t aoff[4], boff[4];
    uint32_t an[4], dsw[4];
#pragma unroll
    for (int i = 0; i < 4; i++) {
        int r = rq + 32 * i;
        dsw[i] = SWZ((uint32_t)(r * 128 + colg * 16));
        bool v = (m0 + r) < cnt;
        aoff[i] = v ? (size_t)(base + m0 + r) * F_DIM : 0;
        an[i]   = v ? 16u : 0u;
        boff[i] = ((size_t)e * D_DIM + d0 + r) * F_DIM;
    }

    float acc[4][4][4];
#pragma unroll
    for (int a = 0; a < 4; a++)
#pragma unroll
        for (int b = 0; b < 4; b++)
#pragma unroll
            for (int c = 0; c < 4; c++) acc[a][b][c] = 0.0f;

    const int NC = F_DIM / 64;  // 64
    const int kbase = colg * 8;
    GEMM_LOAD_CHUNK(0, g_h16, g_w2t, kbase);
    CP_COMMIT();
    GEMM_LOAD_CHUNK(1, g_h16, g_w2t, 64 + kbase);
    CP_COMMIT();

    for (int c = 0; c < NC; c++) {
        CP_WAIT1();
        __syncthreads();
        int cn = c + 2;
        if (cn < NC)
            GEMM_LOAD_CHUNK(cn % 3, g_h16, g_w2t, cn * 64 + kbase);
        CP_COMMIT();
        uint32_t st = sb + (c % 3) * STAGE_BYTES;
        GEMM_COMPUTE_CHUNK(st)
    }

    // epilogue: gate-scaled atomic scatter to out[tok][d]
#pragma unroll
    for (int mi = 0; mi < 4; mi++)
#pragma unroll
        for (int p = 0; p < 2; p++) {
            int gm = m0 + (int)warpM + mi * 16 + (lane >> 2) + 8 * p;
            if (gm < cnt) {
                int   tok = g_rowtok[base + gm];
                float g   = g_rowgate[base + gm];
                float* orow = out + (size_t)tok * D_DIM;
#pragma unroll
                for (int ni = 0; ni < 4; ni++) {
                    int d = d0 + (int)warpN + ni * 8 + 2 * (lane & 3);
                    atomicAdd(orow + d,     g * acc[mi][ni][2 * p]);
                    atomicAdd(orow + d + 1, g * acc[mi][ni][2 * p + 1]);
                }
            }
        }
}

// ---------------- launch ------------------------------------------------------
extern "C" void kernel_launch(void* const* d_in, const int* in_sizes, int n_in,
                              void* d_out, int out_size) {
    const float* x  = (const float*)d_in[0];
    const float* rw = (const float*)d_in[1];
    const float* w1 = (const float*)d_in[2];
    const float* w2 = (const float*)d_in[3];
    float*       out = (float*)d_out;

    static bool init_done = false;
    static cudaStream_t s1, s2;
    static cudaEvent_t ev_root, ev_tw1, ev_tw2;
    if (!init_done) {
        cudaFuncSetAttribute(gemm1_mma, cudaFuncAttributeMaxDynamicSharedMemorySize,
                             SMEM_GEMM);
        cudaFuncSetAttribute(gemm2_mma, cudaFuncAttributeMaxDynamicSharedMemorySize,
                             SMEM_GEMM);
        cudaStreamCreateWithFlags(&s1, cudaStreamNonBlocking);
        cudaStreamCreateWithFlags(&s2, cudaStreamNonBlocking);
        cudaEventCreateWithFlags(&ev_root, cudaEventDisableTiming);
        cudaEventCreateWithFlags(&ev_tw1, cudaEventDisableTiming);
        cudaEventCreateWithFlags(&ev_tw2, cudaEventDisableTiming);
        init_done = true;
    }

    // fork: weight transposes on side streams, token pipeline on main stream
    cudaEventRecord(ev_root, 0);
    cudaStreamWaitEvent(s1, ev_root, 0);
    cudaStreamWaitEvent(s2, ev_root, 0);

    tw1_kernel<<<dim3(F_DIM / 32, D_DIM / 32, E_NUM), dim3(32, 8), 0, s1>>>(w1);
    cudaEventRecord(ev_tw1, s1);
    tw2_kernel<<<dim3(F_DIM / 32, D_DIM / 32, E_NUM), dim3(32, 8), 0, s2>>>(w2);
    cudaEventRecord(ev_tw2, s2);

    conv_x_kernel<<<(T_TOK * D_DIM / 4) / 256, 256>>>(x, out);
    router_kernel<<<(T_TOK * 32) / 256, 256>>>(x, rw);
    offsets_kernel<<<1, 32>>>();
    place_kernel<<<T_TOK / 256, 256>>>();

    // join: gemm1 needs w1t, gemm2 needs w2t
    cudaStreamWaitEvent(0, ev_tw1, 0);
    gemm1_mma<<<dim3(64, F_DIM / 128, E_NUM), 256, SMEM_GEMM>>>();
    cudaStreamWaitEvent(0, ev_tw2, 0);
    gemm2_mma<<<dim3(64, D_DIM / 128, E_NUM), 256, SMEM_GEMM>>>(out);
}

// round 15
// speedup vs baseline: 1.0392x; 1.0392x over previous
#include <cuda_runtime.h>
#include <cuda_fp16.h>
#include <math.h>
#include <stdint.h>

#define T_TOK 8192
#define D_DIM 1024
#define F_DIM 4096
#define E_NUM 8
#define A_TOT (T_TOK * 2)

// ---------------- scratch (device globals; no allocations allowed) ----------
__device__ int   g_cnt[E_NUM];
__device__ int   g_off[E_NUM];
__device__ int   g_cur[E_NUM];
__device__ int   g_top[T_TOK][2];
__device__ float g_gate[T_TOK][2];
__device__ int   g_rowtok[A_TOT];
__device__ float g_rowgate[A_TOT];

// fp16 tensors (raw ushort bits), single plane everywhere
__device__ unsigned short g_x16[(size_t)T_TOK * D_DIM];
__device__ unsigned short g_w1t[(size_t)E_NUM * F_DIM * D_DIM];  // [e][f][d]
__device__ unsigned short g_w2t[(size_t)E_NUM * D_DIM * F_DIM];  // [e][d][f]
__device__ unsigned short g_h16[(size_t)A_TOT * F_DIM];          // [row][f]

// ---------------- helpers -----------------------------------------------------
__device__ __forceinline__ uint32_t smem_u32(const void* p) {
    uint32_t a;
    asm("{ .reg .u64 t; cvta.to.shared.u64 t, %1; cvt.u32.u64 %0, t; }"
        : "=r"(a) : "l"(p));
    return a;
}
#define SWZ(o) ((o) ^ (((o) >> 3) & 0x70))

__device__ __forceinline__ void cpa16(uint32_t d, const void* s, uint32_t n) {
    asm volatile("cp.async.cg.shared.global [%0], [%1], 16, %2;"
                 :: "r"(d), "l"(s), "r"(n) : "memory");
}
#define CP_COMMIT() asm volatile("cp.async.commit_group;" ::: "memory")
#define CP_WAIT1()  asm volatile("cp.async.wait_group 1;" ::: "memory")

#define LDSM4(r, a)                                                      \
    asm volatile("ldmatrix.sync.aligned.m8n8.x4.shared.b16 "             \
                 "{%0,%1,%2,%3}, [%4];"                                  \
                 : "=r"((r)[0]), "=r"((r)[1]), "=r"((r)[2]), "=r"((r)[3])\
                 : "r"(a))

__device__ __forceinline__ void mma16816(float* c, const uint32_t* a,
                                         const uint32_t* b) {
    asm volatile(
        "mma.sync.aligned.m16n8k16.row.col.f32.f16.f16.f32 "
        "{%0,%1,%2,%3}, {%4,%5,%6,%7}, {%8,%9}, {%0,%1,%2,%3};"
        : "+f"(c[0]), "+f"(c[1]), "+f"(c[2]), "+f"(c[3])
        : "r"(a[0]), "r"(a[1]), "r"(a[2]), "r"(a[3]), "r"(b[0]), "r"(b[1]));
}

__device__ __forceinline__ unsigned short to_h16(float v) {
    __half hb = __float2half_rn(v);
    return *reinterpret_cast<unsigned short*>(&hb);
}
__device__ __forceinline__ float gelu_tanh(float v) {
    float c = 0.7978845608028654f * (v + 0.044715f * v * v * v);
    return 0.5f * v * (1.0f + tanhf(c));
}

// ---------------- init + x conversion (fused) ---------------------------------
__global__ void conv_x_kernel(const float* __restrict__ x,
                              float* __restrict__ out) {
    size_t v = (size_t)blockIdx.x * blockDim.x + threadIdx.x;  // float4 idx
    ((float4*)out)[v] = make_float4(0.f, 0.f, 0.f, 0.f);
    float4 f = ((const float4*)x)[v];
    ushort4 h;
    h.x = to_h16(f.x);
    h.y = to_h16(f.y);
    h.z = to_h16(f.z);
    h.w = to_h16(f.w);
    ((ushort4*)g_x16)[v] = h;
    if (blockIdx.x == 0 && threadIdx.x < E_NUM) {
        g_cnt[threadIdx.x] = 0;
        g_cur[threadIdx.x] = 0;
    }
}

// ---------------- router: warp/token, wide coalesced rw loads -----------------
__global__ void router_kernel(const float* __restrict__ x,
                              const float* __restrict__ rw) {
    int gwarp = (blockIdx.x * blockDim.x + threadIdx.x) >> 5;
    int lane  = threadIdx.x & 31;
    if (gwarp >= T_TOK) return;
    const float* xr = x + (size_t)gwarp * D_DIM;

    float logits[E_NUM];
#pragma unroll
    for (int e = 0; e < E_NUM; e++) logits[e] = 0.0f;

#pragma unroll
    for (int i = 0; i < 32; i++) {
        int k = lane + 32 * i;
        float xv = xr[k];
        float4 r0 = *(const float4*)(rw + (size_t)k * E_NUM);
        float4 r1 = *(const float4*)(rw + (size_t)k * E_NUM + 4);
        logits[0] += xv * r0.x;
        logits[1] += xv * r0.y;
        logits[2] += xv * r0.z;
        logits[3] += xv * r0.w;
        logits[4] += xv * r1.x;
        logits[5] += xv * r1.y;
        logits[6] += xv * r1.z;
        logits[7] += xv * r1.w;
    }
#pragma unroll
    for (int e = 0; e < E_NUM; e++) {
#pragma unroll
        for (int o = 16; o > 0; o >>= 1)
            logits[e] += __shfl_xor_sync(0xffffffffu, logits[e], o);
    }

    if (lane == 0) {
        int i0 = 0;
#pragma unroll
        for (int e = 1; e < E_NUM; e++)
            if (logits[e] > logits[i0]) i0 = e;
        int i1 = (i0 == 0) ? 1 : 0;
#pragma unroll
        for (int e = 0; e < E_NUM; e++) {
            if (e == i0) continue;
            if (logits[e] > logits[i1]) i1 = e;
        }
        float g0 = 1.0f / (1.0f + expf(logits[i1] - logits[i0]));
        float g1 = 1.0f - g0;
        g_top[gwarp][0]  = i0;
        g_top[gwarp][1]  = i1;
        g_gate[gwarp][0] = g0;
        g_gate[gwarp][1] = g1;
        atomicAdd(&g_cnt[i0], 1);
        atomicAdd(&g_cnt[i1], 1);
    }
}

__global__ void offsets_kernel() {
    if (threadIdx.x == 0 && blockIdx.x == 0) {
        int run = 0;
#pragma unroll
        for (int e = 0; e < E_NUM; e++) {
            g_off[e] = run;
            run += g_cnt[e];
            g_cur[e] = 0;
        }
    }
}

__global__ void place_kernel() {
    int t = blockIdx.x * blockDim.x + threadIdx.x;
    if (t >= T_TOK) return;
#pragma unroll
    for (int s = 0; s < 2; s++) {
        int e = g_top[t][s];
        int p = g_off[e] + atomicAdd(&g_cur[e], 1);
        g_rowtok[p]  = t;
        g_rowgate[p] = g_gate[t][s];
    }
}

// ---------------- weight transposes (fp32 -> fp16, K-major) -------------------
__global__ void tw1_kernel(const float* __restrict__ w1) {
    __shared__ float t[32][33];
    int e = blockIdx.z, f0 = blockIdx.x * 32, d0 = blockIdx.y * 32;
    int tx = threadIdx.x, ty = threadIdx.y;
#pragma unroll
    for (int r = 0; r < 4; r++)
        t[ty + 8 * r][tx] =
            w1[((size_t)e * D_DIM + d0 + ty + 8 * r) * F_DIM + f0 + tx];
    __syncthreads();
#pragma unroll
    for (int r = 0; r < 4; r++) {
        float v = t[tx][ty + 8 * r];  // = w1[e][d0+tx][f0+ty+8r]
        size_t idx = ((size_t)e * F_DIM + f0 + ty + 8 * r) * D_DIM + d0 + tx;
        g_w1t[idx] = to_h16(v);
    }
}

__global__ void tw2_kernel(const float* __restrict__ w2) {
    __shared__ float t[32][33];
    int e = blockIdx.z, f0 = blockIdx.x * 32, d0 = blockIdx.y * 32;
    int tx = threadIdx.x, ty = threadIdx.y;
#pragma unroll
    for (int r = 0; r < 4; r++)
        t[ty + 8 * r][tx] =
            w2[((size_t)e * F_DIM + f0 + ty + 8 * r) * D_DIM + d0 + tx];
    __syncthreads();
#pragma unroll
    for (int r = 0; r < 4; r++) {
        float v = t[tx][ty + 8 * r];  // = w2[e][f0+tx][d0+ty+8r]
        size_t idx = ((size_t)e * D_DIM + d0 + ty + 8 * r) * F_DIM + f0 + tx;
        g_w2t[idx] = to_h16(v);
    }
}

// ---------------- fp16 mma GEMM core ------------------------------------------
// CTA tile 128x128, K-chunk 64 (128B rows, SW128), 8 warps (2M x 4N),
// warp tile 64x32, 3-stage cp.async pipeline, 1 MMA per (mi,ni,k16).
// 2 CTAs/SM for latency hiding. B loaded with x4 ldmatrix.
#define STAGE_BYTES 32768
#define SOFF_A 0
#define SOFF_B 16384
#define NSTAGE 3
#define SMEM_GEMM (NSTAGE * STAGE_BYTES)

#define GEMM_COMPUTE_CHUNK(st)                                               \
    _Pragma("unroll")                                                        \
    for (int ks = 0; ks < 4; ks++) {                                         \
        uint32_t av[4][4], bbf[2][4];                                        \
        uint32_t arow = warpM + (lane & 15);                                 \
        uint32_t acol = ks * 32 + ((lane >> 4) << 4);                        \
        _Pragma("unroll")                                                    \
        for (int mi = 0; mi < 4; mi++) {                                     \
            uint32_t ad = (st) + SOFF_A + SWZ((arow + 16 * mi) * 128 + acol);\
            LDSM4(av[mi], ad);                                               \
        }                                                                    \
        uint32_t bni = (lane >> 4) << 3;                                     \
        uint32_t bkh = ((lane >> 3) & 1) << 4;                               \
        _Pragma("unroll")                                                    \
        for (int nip = 0; nip < 2; nip++) {                                  \
            uint32_t bd = (st) + SOFF_B +                                    \
                SWZ((warpN + 16 * nip + bni + (lane & 7)) * 128 +            \
                    ks * 32 + bkh);                                          \
            LDSM4(bbf[nip], bd);                                             \
        }                                                                    \
        _Pragma("unroll")                                                    \
        for (int ni = 0; ni < 4; ni++)                                       \
            _Pragma("unroll")                                                \
            for (int mi = 0; mi < 4; mi++)                                   \
                mma16816(acc[mi][ni], av[mi], &bbf[ni >> 1][2 * (ni & 1)]);  \
    }

#define GEMM_LOAD_CHUNK(stage, pa, pb, k0)                                   \
    {                                                                        \
        uint32_t st_ = sb + (stage) * STAGE_BYTES;                           \
        _Pragma("unroll")                                                    \
        for (int i = 0; i < 4; i++) {                                        \
            cpa16(st_ + SOFF_A + dsw[i], (pa) + aoff[i] + (k0), an[i]);      \
            cpa16(st_ + SOFF_B + dsw[i], (pb) + boff[i] + (k0), 16u);        \
        }                                                                    \
    }

// ---------------- GEMM1: H = gelu(gather(X) @ w1t[e]^T) -----------------------
__global__ __launch_bounds__(256, 2) void gemm1_mma() {
    const int e   = blockIdx.z;
    const int cnt = g_cnt[e];
    const int m0  = blockIdx.x * 128;
    if (m0 >= cnt) return;
    const int base = g_off[e];
    const int n0   = blockIdx.y * 128;

    extern __shared__ char smem[];
    const uint32_t sb = smem_u32(smem);
    const int tid = threadIdx.x, lane = tid & 31, wid = tid >> 5;
    const uint32_t warpM = (wid & 1) * 64, warpN = (wid >> 1) * 32;

    const int colg = tid & 7;
    const int rq   = tid >> 3;
    size_t aoff[4], boff[4];
    uint32_t an[4], dsw[4];
#pragma unroll
    for (int i = 0; i < 4; i++) {
        int r = rq + 32 * i;
        dsw[i] = SWZ((uint32_t)(r * 128 + colg * 16));
        bool v = (m0 + r) < cnt;
        aoff[i] = v ? (size_t)g_rowtok[base + m0 + r] * D_DIM : 0;
        an[i]   = v ? 16u : 0u;
        boff[i] = ((size_t)e * F_DIM + n0 + r) * D_DIM;
    }

    float acc[4][4][4];
#pragma unroll
    for (int a = 0; a < 4; a++)
#pragma unroll
        for (int b = 0; b < 4; b++)
#pragma unroll
            for (int c = 0; c < 4; c++) acc[a][b][c] = 0.0f;

    const int NC = D_DIM / 64;  // 16
    const int kbase = colg * 8;
    GEMM_LOAD_CHUNK(0, g_x16, g_w1t, kbase);
    CP_COMMIT();
    GEMM_LOAD_CHUNK(1, g_x16, g_w1t, 64 + kbase);
    CP_COMMIT();

    for (int c = 0; c < NC; c++) {
        CP_WAIT1();
        __syncthreads();
        int cn = c + 2;
        if (cn < NC)
            GEMM_LOAD_CHUNK(cn % 3, g_x16, g_w1t, cn * 64 + kbase);
        CP_COMMIT();
        uint32_t st = sb + (c % 3) * STAGE_BYTES;
        GEMM_COMPUTE_CHUNK(st)
    }

    // epilogue: gelu -> fp16 -> store to g_h16
#pragma unroll
    for (int mi = 0; mi < 4; mi++)
#pragma unroll
        for (int p = 0; p < 2; p++) {
            int gm = m0 + (int)warpM + mi * 16 + (lane >> 2) + 8 * p;
            if (gm < cnt) {
                size_t rb = (size_t)(base + gm) * F_DIM;
#pragma unroll
                for (int ni = 0; ni < 4; ni++) {
                    int n = n0 + (int)warpN + ni * 8 + 2 * (lane & 3);
                    float v0 = gelu_tanh(acc[mi][ni][2 * p]);
                    float v1 = gelu_tanh(acc[mi][ni][2 * p + 1]);
                    *(ushort2*)(g_h16 + rb + n) =
                        make_ushort2(to_h16(v0), to_h16(v1));
                }
            }
        }
}

// ---------------- GEMM2: out[tok] += gate * (H @ w2t[e]^T) --------------------
__global__ __launch_bounds__(256, 2) void gemm2_mma(float* __restrict__ out) {
    const int e   = blockIdx.z;
    const int cnt = g_cnt[e];
    const int m0  = blockIdx.x * 128;
    if (m0 >= cnt) return;
    const int base = g_off[e];
    const int d0   = blockIdx.y * 128;

    extern __shared__ char smem[];
    const uint32_t sb = smem_u32(smem);
    const int tid = threadIdx.x, lane = tid & 31, wid = tid >> 5;
    const uint32_t warpM = (wid & 1) * 64, warpN = (wid >> 1) * 32;

    const int colg = tid & 7;
    const int rq   = tid >> 3;
    size_t aoff[4], boff[4];
    uint32_t an[4], dsw[4];
#pragma unroll
    for (int i = 0; i < 4; i++) {
        int r = rq + 32 * i;
        dsw[i] = SWZ((uint32_t)(r * 128 + colg * 16));
        bool v = (m0 + r) < cnt;
        aoff[i] = v ? (size_t)(base + m0 + r) * F_DIM : 0;
        an[i]   = v ? 16u : 0u;
        boff[i] = ((size_t)e * D_DIM + d0 + r) * F_DIM;
    }

    float acc[4][4][4];
#pragma unroll
    for (int a = 0; a < 4; a++)
#pragma unroll
        for (int b = 0; b < 4; b++)
#pragma unroll
            for (int c = 0; c < 4; c++) acc[a][b][c] = 0.0f;

    const int NC = F_DIM / 64;  // 64
    const int kbase = colg * 8;
    GEMM_LOAD_CHUNK(0, g_h16, g_w2t, kbase);
    CP_COMMIT();
    GEMM_LOAD_CHUNK(1, g_h16, g_w2t, 64 + kbase);
    CP_COMMIT();

    for (int c = 0; c < NC; c++) {
        CP_WAIT1();
        __syncthreads();
        int cn = c + 2;
        if (cn < NC)
            GEMM_LOAD_CHUNK(cn % 3, g_h16, g_w2t, cn * 64 + kbase);
        CP_COMMIT();
        uint32_t st = sb + (c % 3) * STAGE_BYTES;
        GEMM_COMPUTE_CHUNK(st)
    }

    // epilogue: gate-scaled atomic scatter to out[tok][d]
#pragma unroll
    for (int mi = 0; mi < 4; mi++)
#pragma unroll
        for (int p = 0; p < 2; p++) {
            int gm = m0 + (int)warpM + mi * 16 + (lane >> 2) + 8 * p;
            if (gm < cnt) {
                int   tok = g_rowtok[base + gm];
                float g   = g_rowgate[base + gm];
                float* orow = out + (size_t)tok * D_DIM;
#pragma unroll
                for (int ni = 0; ni < 4; ni++) {
                    int d = d0 + (int)warpN + ni * 8 + 2 * (lane & 3);
                    atomicAdd(orow + d,     g * acc[mi][ni][2 * p]);
                    atomicAdd(orow + d + 1, g * acc[mi][ni][2 * p + 1]);
                }
            }
        }
}

// ---------------- launch ------------------------------------------------------
extern "C" void kernel_launch(void* const* d_in, const int* in_sizes, int n_in,
                              void* d_out, int out_size) {
    const float* x  = (const float*)d_in[0];
    const float* rw = (const float*)d_in[1];
    const float* w1 = (const float*)d_in[2];
    const float* w2 = (const float*)d_in[3];
    float*       out = (float*)d_out;

    static bool init_done = false;
    static cudaStream_t s1, s2;
    static cudaEvent_t ev_root, ev_tw1, ev_tw2;
    if (!init_done) {
        cudaFuncSetAttribute(gemm1_mma, cudaFuncAttributeMaxDynamicSharedMemorySize,
                             SMEM_GEMM);
        cudaFuncSetAttribute(gemm2_mma, cudaFuncAttributeMaxDynamicSharedMemorySize,
                             SMEM_GEMM);
        cudaStreamCreateWithFlags(&s1, cudaStreamNonBlocking);
        cudaStreamCreateWithFlags(&s2, cudaStreamNonBlocking);
        cudaEventCreateWithFlags(&ev_root, cudaEventDisableTiming);
        cudaEventCreateWithFlags(&ev_tw1, cudaEventDisableTiming);
        cudaEventCreateWithFlags(&ev_tw2, cudaEventDisableTiming);
        init_done = true;
    }

    // fork: weight transposes on side streams, token pipeline on main stream
    cudaEventRecord(ev_root, 0);
    cudaStreamWaitEvent(s1, ev_root, 0);
    cudaStreamWaitEvent(s2, ev_root, 0);

    tw1_kernel<<<dim3(F_DIM / 32, D_DIM / 32, E_NUM), dim3(32, 8), 0, s1>>>(w1);
    cudaEventRecord(ev_tw1, s1);
    tw2_kernel<<<dim3(F_DIM / 32, D_DIM / 32, E_NUM), dim3(32, 8), 0, s2>>>(w2);
    cudaEventRecord(ev_tw2, s2);

    conv_x_kernel<<<(T_TOK * D_DIM / 4) / 256, 256>>>(x, out);
    router_kernel<<<(T_TOK * 32) / 256, 256>>>(x, rw);
    offsets_kernel<<<1, 32>>>();
    place_kernel<<<T_TOK / 256, 256>>>();

    // join: gemm1 needs w1t, gemm2 needs w2t
    cudaStreamWaitEvent(0, ev_tw1, 0);
    gemm1_mma<<<dim3(64, F_DIM / 128, E_NUM), 256, SMEM_GEMM>>>();
    cudaStreamWaitEvent(0, ev_tw2, 0);
    gemm2_mma<<<dim3(64, D_DIM / 128, E_NUM), 256, SMEM_GEMM>>>(out);
}

// round 16
// speedup vs baseline: 1.0470x; 1.0075x over previous
#include <cuda_runtime.h>
#include <cuda_fp16.h>
#include <math.h>
#include <stdint.h>

#define T_TOK 8192
#define D_DIM 1024
#define F_DIM 4096
#define E_NUM 8
#define A_TOT (T_TOK * 2)

// ---------------- scratch (device globals; no allocations allowed) ----------
__device__ int   g_cnt[E_NUM];
__device__ int   g_off[E_NUM];
__device__ int   g_cur[E_NUM];
__device__ int   g_top[T_TOK][2];
__device__ float g_gate[T_TOK][2];
__device__ int   g_rowtok[A_TOT];
__device__ float g_rowgate[A_TOT];

// fp16 tensors (raw ushort bits), single plane everywhere
__device__ unsigned short g_x16[(size_t)T_TOK * D_DIM];
__device__ unsigned short g_w1t[(size_t)E_NUM * F_DIM * D_DIM];  // [e][f][d]
__device__ unsigned short g_w2t[(size_t)E_NUM * D_DIM * F_DIM];  // [e][d][f]
__device__ unsigned short g_h16[(size_t)A_TOT * F_DIM];          // [row][f]

// ---------------- helpers -----------------------------------------------------
__device__ __forceinline__ uint32_t smem_u32(const void* p) {
    uint32_t a;
    asm("{ .reg .u64 t; cvta.to.shared.u64 t, %1; cvt.u32.u64 %0, t; }"
        : "=r"(a) : "l"(p));
    return a;
}
#define SWZ(o) ((o) ^ (((o) >> 3) & 0x70))

__device__ __forceinline__ void cpa16(uint32_t d, const void* s, uint32_t n) {
    asm volatile("cp.async.cg.shared.global [%0], [%1], 16, %2;"
                 :: "r"(d), "l"(s), "r"(n) : "memory");
}
#define CP_COMMIT() asm volatile("cp.async.commit_group;" ::: "memory")
#define CP_WAIT1()  asm volatile("cp.async.wait_group 1;" ::: "memory")

#define LDSM4(r, a)                                                      \
    asm volatile("ldmatrix.sync.aligned.m8n8.x4.shared.b16 "             \
                 "{%0,%1,%2,%3}, [%4];"                                  \
                 : "=r"((r)[0]), "=r"((r)[1]), "=r"((r)[2]), "=r"((r)[3])\
                 : "r"(a))

__device__ __forceinline__ void mma16816(float* c, const uint32_t* a,
                                         const uint32_t* b) {
    asm volatile(
        "mma.sync.aligned.m16n8k16.row.col.f32.f16.f16.f32 "
        "{%0,%1,%2,%3}, {%4,%5,%6,%7}, {%8,%9}, {%0,%1,%2,%3};"
        : "+f"(c[0]), "+f"(c[1]), "+f"(c[2]), "+f"(c[3])
        : "r"(a[0]), "r"(a[1]), "r"(a[2]), "r"(a[3]), "r"(b[0]), "r"(b[1]));
}

// vector float2 reduction add (sm_90+ baseline PTX)
__device__ __forceinline__ void red_add_v2(float* addr, float a, float b) {
    asm volatile("red.global.add.v2.f32 [%0], {%1, %2};"
                 :: "l"(addr), "f"(a), "f"(b) : "memory");
}

__device__ __forceinline__ unsigned short to_h16(float v) {
    __half hb = __float2half_rn(v);
    return *reinterpret_cast<unsigned short*>(&hb);
}
__device__ __forceinline__ float gelu_tanh(float v) {
    float c = 0.7978845608028654f * (v + 0.044715f * v * v * v);
    return 0.5f * v * (1.0f + tanhf(c));
}

// ---------------- init + x conversion (fused) ---------------------------------
__global__ void conv_x_kernel(const float* __restrict__ x,
                              float* __restrict__ out) {
    size_t v = (size_t)blockIdx.x * blockDim.x + threadIdx.x;  // float4 idx
    ((float4*)out)[v] = make_float4(0.f, 0.f, 0.f, 0.f);
    float4 f = ((const float4*)x)[v];
    ushort4 h;
    h.x = to_h16(f.x);
    h.y = to_h16(f.y);
    h.z = to_h16(f.z);
    h.w = to_h16(f.w);
    ((ushort4*)g_x16)[v] = h;
    if (blockIdx.x == 0 && threadIdx.x < E_NUM) {
        g_cnt[threadIdx.x] = 0;
        g_cur[threadIdx.x] = 0;
    }
}

// ---------------- router: warp/token, wide coalesced rw loads -----------------
__global__ void router_kernel(const float* __restrict__ x,
                              const float* __restrict__ rw) {
    int gwarp = (blockIdx.x * blockDim.x + threadIdx.x) >> 5;
    int lane  = threadIdx.x & 31;
    if (gwarp >= T_TOK) return;
    const float* xr = x + (size_t)gwarp * D_DIM;

    float logits[E_NUM];
#pragma unroll
    for (int e = 0; e < E_NUM; e++) logits[e] = 0.0f;

#pragma unroll
    for (int i = 0; i < 32; i++) {
        int k = lane + 32 * i;
        float xv = xr[k];
        float4 r0 = *(const float4*)(rw + (size_t)k * E_NUM);
        float4 r1 = *(const float4*)(rw + (size_t)k * E_NUM + 4);
        logits[0] += xv * r0.x;
        logits[1] += xv * r0.y;
        logits[2] += xv * r0.z;
        logits[3] += xv * r0.w;
        logits[4] += xv * r1.x;
        logits[5] += xv * r1.y;
        logits[6] += xv * r1.z;
        logits[7] += xv * r1.w;
    }
#pragma unroll
    for (int e = 0; e < E_NUM; e++) {
#pragma unroll
        for (int o = 16; o > 0; o >>= 1)
            logits[e] += __shfl_xor_sync(0xffffffffu, logits[e], o);
    }

    if (lane == 0) {
        int i0 = 0;
#pragma unroll
        for (int e = 1; e < E_NUM; e++)
            if (logits[e] > logits[i0]) i0 = e;
        int i1 = (i0 == 0) ? 1 : 0;
#pragma unroll
        for (int e = 0; e < E_NUM; e++) {
            if (e == i0) continue;
            if (logits[e] > logits[i1]) i1 = e;
        }
        float g0 = 1.0f / (1.0f + expf(logits[i1] - logits[i0]));
        float g1 = 1.0f - g0;
        g_top[gwarp][0]  = i0;
        g_top[gwarp][1]  = i1;
        g_gate[gwarp][0] = g0;
        g_gate[gwarp][1] = g1;
        atomicAdd(&g_cnt[i0], 1);
        atomicAdd(&g_cnt[i1], 1);
    }
}

__global__ void offsets_kernel() {
    if (threadIdx.x == 0 && blockIdx.x == 0) {
        int run = 0;
#pragma unroll
        for (int e = 0; e < E_NUM; e++) {
            g_off[e] = run;
            run += g_cnt[e];
            g_cur[e] = 0;
        }
    }
}

__global__ void place_kernel() {
    int t = blockIdx.x * blockDim.x + threadIdx.x;
    if (t >= T_TOK) return;
#pragma unroll
    for (int s = 0; s < 2; s++) {
        int e = g_top[t][s];
        int p = g_off[e] + atomicAdd(&g_cur[e], 1);
        g_rowtok[p]  = t;
        g_rowgate[p] = g_gate[t][s];
    }
}

// ---------------- weight transposes (fp32 -> fp16, K-major) -------------------
__global__ void tw1_kernel(const float* __restrict__ w1) {
    __shared__ float t[32][33];
    int e = blockIdx.z, f0 = blockIdx.x * 32, d0 = blockIdx.y * 32;
    int tx = threadIdx.x, ty = threadIdx.y;
#pragma unroll
    for (int r = 0; r < 4; r++)
        t[ty + 8 * r][tx] =
            w1[((size_t)e * D_DIM + d0 + ty + 8 * r) * F_DIM + f0 + tx];
    __syncthreads();
#pragma unroll
    for (int r = 0; r < 4; r++) {
        float v = t[tx][ty + 8 * r];  // = w1[e][d0+tx][f0+ty+8r]
        size_t idx = ((size_t)e * F_DIM + f0 + ty + 8 * r) * D_DIM + d0 + tx;
        g_w1t[idx] = to_h16(v);
    }
}

__global__ void tw2_kernel(const float* __restrict__ w2) {
    __shared__ float t[32][33];
    int e = blockIdx.z, f0 = blockIdx.x * 32, d0 = blockIdx.y * 32;
    int tx = threadIdx.x, ty = threadIdx.y;
#pragma unroll
    for (int r = 0; r < 4; r++)
        t[ty + 8 * r][tx] =
            w2[((size_t)e * F_DIM + f0 + ty + 8 * r) * D_DIM + d0 + tx];
    __syncthreads();
#pragma unroll
    for (int r = 0; r < 4; r++) {
        float v = t[tx][ty + 8 * r];  // = w2[e][f0+tx][d0+ty+8r]
        size_t idx = ((size_t)e * D_DIM + d0 + ty + 8 * r) * F_DIM + f0 + tx;
        g_w2t[idx] = to_h16(v);
    }
}

// ---------------- fp16 mma GEMM core ------------------------------------------
// CTA tile 128x128, K-chunk 64 (128B rows, SW128), 8 warps (2M x 4N),
// warp tile 64x32, 3-stage cp.async pipeline, 1 MMA per (mi,ni,k16).
// 2 CTAs/SM for latency hiding. B loaded with x4 ldmatrix.
#define STAGE_BYTES 32768
#define SOFF_A 0
#define SOFF_B 16384
#define NSTAGE 3
#define SMEM_GEMM (NSTAGE * STAGE_BYTES)

#define GEMM_COMPUTE_CHUNK(st)                                               \
    _Pragma("unroll")                                                        \
    for (int ks = 0; ks < 4; ks++) {                                         \
        uint32_t av[4][4], bbf[2][4];                                        \
        uint32_t arow = warpM + (lane & 15);                                 \
        uint32_t acol = ks * 32 + ((lane >> 4) << 4);                        \
        _Pragma("unroll")                                                    \
        for (int mi = 0; mi < 4; mi++) {                                     \
            uint32_t ad = (st) + SOFF_A + SWZ((arow + 16 * mi) * 128 + acol);\
            LDSM4(av[mi], ad);                                               \
        }                                                                    \
        uint32_t bni = (lane >> 4) << 3;                                     \
        uint32_t bkh = ((lane >> 3) & 1) << 4;                               \
        _Pragma("unroll")                                                    \
        for (int nip = 0; nip < 2; nip++) {                                  \
            uint32_t bd = (st) + SOFF_B +                                    \
                SWZ((warpN + 16 * nip + bni + (lane & 7)) * 128 +            \
                    ks * 32 + bkh);                                          \
            LDSM4(bbf[nip], bd);                                             \
        }                                                                    \
        _Pragma("unroll")                                                    \
        for (int ni = 0; ni < 4; ni++)                                       \
            _Pragma("unroll")                                                \
            for (int mi = 0; mi < 4; mi++)                                   \
                mma16816(acc[mi][ni], av[mi], &bbf[ni >> 1][2 * (ni & 1)]);  \
    }

#define GEMM_LOAD_CHUNK(stage, pa, pb, k0)                                   \
    {                                                                        \
        uint32_t st_ = sb + (stage) * STAGE_BYTES;                           \
        _Pragma("unroll")                                                    \
        for (int i = 0; i < 4; i++) {                                        \
            cpa16(st_ + SOFF_A + dsw[i], (pa) + aoff[i] + (k0), an[i]);      \
            cpa16(st_ + SOFF_B + dsw[i], (pb) + boff[i] + (k0), 16u);        \
        }                                                                    \
    }

// ---------------- GEMM1: H = gelu(gather(X) @ w1t[e]^T) -----------------------
__global__ __launch_bounds__(256, 2) void gemm1_mma() {
    const int e   = blockIdx.z;
    const int cnt = g_cnt[e];
    const int m0  = blockIdx.x * 128;
    if (m0 >= cnt) return;
    const int base = g_off[e];
    const int n0   = blockIdx.y * 128;

    extern __shared__ char smem[];
    const uint32_t sb = smem_u32(smem);
    const int tid = threadIdx.x, lane = tid & 31, wid = tid >> 5;
    const uint32_t warpM = (wid & 1) * 64, warpN = (wid >> 1) * 32;

    const int colg = tid & 7;
    const int rq   = tid >> 3;
    size_t aoff[4], boff[4];
    uint32_t an[4], dsw[4];
#pragma unroll
    for (int i = 0; i < 4; i++) {
        int r = rq + 32 * i;
        dsw[i] = SWZ((uint32_t)(r * 128 + colg * 16));
        bool v = (m0 + r) < cnt;
        aoff[i] = v ? (size_t)g_rowtok[base + m0 + r] * D_DIM : 0;
        an[i]   = v ? 16u : 0u;
        boff[i] = ((size_t)e * F_DIM + n0 + r) * D_DIM;
    }

    float acc[4][4][4];
#pragma unroll
    for (int a = 0; a < 4; a++)
#pragma unroll
        for (int b = 0; b < 4; b++)
#pragma unroll
            for (int c = 0; c < 4; c++) acc[a][b][c] = 0.0f;

    const int NC = D_DIM / 64;  // 16
    const int kbase = colg * 8;
    GEMM_LOAD_CHUNK(0, g_x16, g_w1t, kbase);
    CP_COMMIT();
    GEMM_LOAD_CHUNK(1, g_x16, g_w1t, 64 + kbase);
    CP_COMMIT();

    for (int c = 0; c < NC; c++) {
        CP_WAIT1();
        __syncthreads();
        int cn = c + 2;
        if (cn < NC)
            GEMM_LOAD_CHUNK(cn % 3, g_x16, g_w1t, cn * 64 + kbase);
        CP_COMMIT();
        uint32_t st = sb + (c % 3) * STAGE_BYTES;
        GEMM_COMPUTE_CHUNK(st)
    }

    // epilogue: gelu -> fp16 -> store to g_h16
#pragma unroll
    for (int mi = 0; mi < 4; mi++)
#pragma unroll
        for (int p = 0; p < 2; p++) {
            int gm = m0 + (int)warpM + mi * 16 + (lane >> 2) + 8 * p;
            if (gm < cnt) {
                size_t rb = (size_t)(base + gm) * F_DIM;
#pragma unroll
                for (int ni = 0; ni < 4; ni++) {
                    int n = n0 + (int)warpN + ni * 8 + 2 * (lane & 3);
                    float v0 = gelu_tanh(acc[mi][ni][2 * p]);
                    float v1 = gelu_tanh(acc[mi][ni][2 * p + 1]);
                    *(ushort2*)(g_h16 + rb + n) =
                        make_ushort2(to_h16(v0), to_h16(v1));
                }
            }
        }
}

// ---------------- GEMM2: out[tok] += gate * (H @ w2t[e]^T) --------------------
__global__ __launch_bounds__(256, 2) void gemm2_mma(float* __restrict__ out) {
    const int e   = blockIdx.z;
    const int cnt = g_cnt[e];
    const int m0  = blockIdx.x * 128;
    if (m0 >= cnt) return;
    const int base = g_off[e];
    const int d0   = blockIdx.y * 128;

    extern __shared__ char smem[];
    const uint32_t sb = smem_u32(smem);
    const int tid = threadIdx.x, lane = tid & 31, wid = tid >> 5;
    const uint32_t warpM = (wid & 1) * 64, warpN = (wid >> 1) * 32;

    const int colg = tid & 7;
    const int rq   = tid >> 3;
    size_t aoff[4], boff[4];
    uint32_t an[4], dsw[4];
#pragma unroll
    for (int i = 0; i < 4; i++) {
        int r = rq + 32 * i;
        dsw[i] = SWZ((uint32_t)(r * 128 + colg * 16));
        bool v = (m0 + r) < cnt;
        aoff[i] = v ? (size_t)(base + m0 + r) * F_DIM : 0;
        an[i]   = v ? 16u : 0u;
        boff[i] = ((size_t)e * D_DIM + d0 + r) * F_DIM;
    }

    float acc[4][4][4];
#pragma unroll
    for (int a = 0; a < 4; a++)
#pragma unroll
        for (int b = 0; b < 4; b++)
#pragma unroll
            for (int c = 0; c < 4; c++) acc[a][b][c] = 0.0f;

    const int NC = F_DIM / 64;  // 64
    const int kbase = colg * 8;
    GEMM_LOAD_CHUNK(0, g_h16, g_w2t, kbase);
    CP_COMMIT();
    GEMM_LOAD_CHUNK(1, g_h16, g_w2t, 64 + kbase);
    CP_COMMIT();

    for (int c = 0; c < NC; c++) {
        CP_WAIT1();
        __syncthreads();
        int cn = c + 2;
        if (cn < NC)
            GEMM_LOAD_CHUNK(cn % 3, g_h16, g_w2t, cn * 64 + kbase);
        CP_COMMIT();
        uint32_t st = sb + (c % 3) * STAGE_BYTES;
        GEMM_COMPUTE_CHUNK(st)
    }

    // epilogue: gate-scaled vector-reduction scatter to out[tok][d]
#pragma unroll
    for (int mi = 0; mi < 4; mi++)
#pragma unroll
        for (int p = 0; p < 2; p++) {
            int gm = m0 + (int)warpM + mi * 16 + (lane >> 2) + 8 * p;
            if (gm < cnt) {
                int   tok = g_rowtok[base + gm];
                float g   = g_rowgate[base + gm];
                float* orow = out + (size_t)tok * D_DIM;
#pragma unroll
                for (int ni = 0; ni < 4; ni++) {
                    int d = d0 + (int)warpN + ni * 8 + 2 * (lane & 3);
                    red_add_v2(orow + d, g * acc[mi][ni][2 * p],
                               g * acc[mi][ni][2 * p + 1]);
                }
            }
        }
}

// ---------------- launch ------------------------------------------------------
extern "C" void kernel_launch(void* const* d_in, const int* in_sizes, int n_in,
                              void* d_out, int out_size) {
    const float* x  = (const float*)d_in[0];
    const float* rw = (const float*)d_in[1];
    const float* w1 = (const float*)d_in[2];
    const float* w2 = (const float*)d_in[3];
    float*       out = (float*)d_out;

    static bool init_done = false;
    static cudaStream_t s1, s2;
    static cudaEvent_t ev_root, ev_tw1, ev_tw2;
    if (!init_done) {
        cudaFuncSetAttribute(gemm1_mma, cudaFuncAttributeMaxDynamicSharedMemorySize,
                             SMEM_GEMM);
        cudaFuncSetAttribute(gemm2_mma, cudaFuncAttributeMaxDynamicSharedMemorySize,
                             SMEM_GEMM);
        cudaStreamCreateWithFlags(&s1, cudaStreamNonBlocking);
        cudaStreamCreateWithFlags(&s2, cudaStreamNonBlocking);
        cudaEventCreateWithFlags(&ev_root, cudaEventDisableTiming);
        cudaEventCreateWithFlags(&ev_tw1, cudaEventDisableTiming);
        cudaEventCreateWithFlags(&ev_tw2, cudaEventDisableTiming);
        init_done = true;
    }

    // fork: weight transposes on side streams, token pipeline on main stream
    cudaEventRecord(ev_root, 0);
    cudaStreamWaitEvent(s1, ev_root, 0);
    cudaStreamWaitEvent(s2, ev_root, 0);

    tw1_kernel<<<dim3(F_DIM / 32, D_DIM / 32, E_NUM), dim3(32, 8), 0, s1>>>(w1);
    cudaEventRecord(ev_tw1, s1);
    tw2_kernel<<<dim3(F_DIM / 32, D_DIM / 32, E_NUM), dim3(32, 8), 0, s2>>>(w2);
    cudaEventRecord(ev_tw2, s2);

    conv_x_kernel<<<(T_TOK * D_DIM / 4) / 256, 256>>>(x, out);
    router_kernel<<<(T_TOK * 32) / 256, 256>>>(x, rw);
    offsets_kernel<<<1, 32>>>();
    place_kernel<<<T_TOK / 256, 256>>>();

    // join: gemm1 needs w1t, gemm2 needs w2t
    cudaStreamWaitEvent(0, ev_tw1, 0);
    gemm1_mma<<<dim3(64, F_DIM / 128, E_NUM), 256, SMEM_GEMM>>>();
    cudaStreamWaitEvent(0, ev_tw2, 0);
    gemm2_mma<<<dim3(64, D_DIM / 128, E_NUM), 256, SMEM_GEMM>>>(out);
}